// round 6
// baseline (speedup 1.0000x reference)
#include <cuda_runtime.h>
#include <cuda_fp16.h>
#include <cstdint>
#include <cstddef>

// Problem shape (fixed by dataset)
#define NB   8192      // batch rows
#define DIM  4096      // in = out features
#define MAXN 0.99999f  // (1-EPS)/sqrt(C)

// ---------------- scratch (device globals; allocation-free) ----------------
__device__ __half g_xh[(size_t)NB * DIM];
__device__ __half g_wh[(size_t)DIM * DIM];
__device__ float g_xn[NB];     // raw row norms of x
__device__ float g_bm[DIM];    // expmap0(bias)
__device__ float g_y2s[1];     // ||bm||^2

// ---------------- PTX helpers (base sm_103 target ONLY: no tcgen05) --------
__device__ __forceinline__ uint32_t smem_u32(const void* p) {
    uint32_t a;
    asm("{ .reg .u64 t; cvta.to.shared.u64 t, %1; cvt.u32.u64 %0, t; }"
        : "=r"(a) : "l"(p));
    return a;
}

__device__ __forceinline__ void cp16(uint32_t dst, const void* src) {
    asm volatile("cp.async.cg.shared.global [%0], [%1], 16;" :: "r"(dst), "l"(src));
}

__device__ __forceinline__ void ldsm4(uint32_t* r, uint32_t addr) {
    asm volatile("ldmatrix.sync.aligned.m8n8.x4.shared.b16 {%0,%1,%2,%3}, [%4];"
                 : "=r"(r[0]), "=r"(r[1]), "=r"(r[2]), "=r"(r[3]) : "r"(addr));
}

__device__ __forceinline__ void mma_f16(float* c, const uint32_t* a,
                                        uint32_t b0, uint32_t b1) {
    asm volatile(
        "mma.sync.aligned.m16n8k16.row.col.f32.f16.f16.f32 "
        "{%0,%1,%2,%3}, {%4,%5,%6,%7}, {%8,%9}, {%0,%1,%2,%3};"
        : "+f"(c[0]), "+f"(c[1]), "+f"(c[2]), "+f"(c[3])
        : "r"(a[0]), "r"(a[1]), "r"(a[2]), "r"(a[3]), "r"(b0), "r"(b1));
}

#define SWZ(o) ((o) ^ (((o) >> 3) & 0x70))

// ---------------- pre-kernels ----------------
__global__ void k_conv_x(const float* __restrict__ x) {
    int r = blockIdx.x;
    const float4* row = (const float4*)(x + (size_t)r * DIM);
    __half2* orow = (__half2*)(g_xh + (size_t)r * DIM);
    float ss = 0.f;
    #pragma unroll
    for (int it = 0; it < 4; it++) {
        int c = it * 256 + threadIdx.x;
        float4 v = row[c];
        ss += v.x * v.x + v.y * v.y + v.z * v.z + v.w * v.w;
        orow[2 * c]     = __floats2half2_rn(v.x, v.y);
        orow[2 * c + 1] = __floats2half2_rn(v.z, v.w);
    }
    __shared__ float red[8];
    #pragma unroll
    for (int off = 16; off; off >>= 1) ss += __shfl_down_sync(0xffffffffu, ss, off);
    if ((threadIdx.x & 31) == 0) red[threadIdx.x >> 5] = ss;
    __syncthreads();
    if (threadIdx.x == 0) {
        float t = 0.f;
        #pragma unroll
        for (int i = 0; i < 8; i++) t += red[i];
        g_xn[r] = sqrtf(t);
    }
}

__global__ void k_conv_w(const float* __restrict__ w) {
    size_t n = (size_t)DIM * DIM / 4;
    const float4* w4 = (const float4*)w;
    __half2* o2 = (__half2*)g_wh;
    for (size_t i = (size_t)blockIdx.x * blockDim.x + threadIdx.x; i < n;
         i += (size_t)gridDim.x * blockDim.x) {
        float4 v = w4[i];
        o2[2 * i]     = __floats2half2_rn(v.x, v.y);
        o2[2 * i + 1] = __floats2half2_rn(v.z, v.w);
    }
}

__global__ void k_bias(const float* __restrict__ bias) {
    __shared__ float red[8];
    __shared__ float s_t;
    float ss = 0.f;
    for (int c = threadIdx.x; c < DIM; c += 256) { float v = bias[c]; ss += v * v; }
    #pragma unroll
    for (int off = 16; off; off >>= 1) ss += __shfl_down_sync(0xffffffffu, ss, off);
    if ((threadIdx.x & 31) == 0) red[threadIdx.x >> 5] = ss;
    __syncthreads();
    if (threadIdx.x == 0) {
        float t = 0.f;
        #pragma unroll
        for (int i = 0; i < 8; i++) t += red[i];
        float bn = fmaxf(sqrtf(t), 1e-15f);
        float th = tanhf(bn);
        s_t = th / bn;
        g_y2s[0] = th * th;
    }
    __syncthreads();
    float sc = s_t;
    for (int c = threadIdx.x; c < DIM; c += 256) g_bm[c] = sc * bias[c];
}

// ---------------- GEMM: mx_raw = x @ W^T, single fp16 pass ----------------
// CTA tile 128(M) x 128(N) x 64(K), 4 warps (2x2, warp tile 64x64), 2-stage
// cp.async, 3 CTAs/SM (12 warps/SM, 3 per SMSP; ldsm ratio 0.0625 B/MAC).
// K = 4096 -> 64 BK iterations.
#define NKIT   64
#define A_ST_BYTES 16384           // 128 rows x 128B
#define B_ST_BYTES 16384           // 128 rows x 128B
#define ST_BYTES   (A_ST_BYTES + B_ST_BYTES)   // 32 KB
#define SMEM_NEED  (2 * ST_BYTES + 1024)       // ~65 KB -> 3 CTAs/SM

__global__ void __launch_bounds__(128, 3)
k_gemm(float* __restrict__ out) {
    extern __shared__ char dsm[];
    uint32_t base = (smem_u32(dsm) + 1023u) & ~1023u;
    const int tid = threadIdx.x;
    const int wid = tid >> 5;
    const int lane = tid & 31;
    const int wm = wid >> 1;          // 0..1  (M direction, 64 rows each)
    const int wn = wid & 1;           // 0..1  (N direction, 64 cols each)

    // rasterize 64 x 32 tiles in 8x32 supertiles for L2 reuse
    int pid = blockIdx.x;
    int group = pid >> 8;             // / (8*32)
    int rem = pid & 255;
    int pm = group * 8 + (rem & 7);
    int pn = rem >> 3;
    const int m0 = pm * 128, n0 = pn * 128;

    auto load_stage = [&](int s, int i) {
        int koff = i * 64;                              // element offset in K
        const char* ab = (const char*)g_xh;
        const char* bb = (const char*)g_wh;
        size_t aBase = ((size_t)m0 * DIM + koff) * 2;
        size_t bBase = ((size_t)n0 * DIM + koff) * 2;
        uint32_t as = base + s * ST_BYTES;
        uint32_t bs = as + A_ST_BYTES;
        #pragma unroll
        for (int t = 0; t < 8; t++) {                   // A: 1024 chunks of 16B
            int chunk = t * 128 + tid;
            int row = chunk >> 3, c16 = chunk & 7;
            cp16(as + SWZ(row * 128 + c16 * 16),
                 ab + aBase + (size_t)row * (DIM * 2) + c16 * 16);
        }
        #pragma unroll
        for (int t = 0; t < 8; t++) {                   // B: 1024 chunks of 16B
            int chunk = t * 128 + tid;
            int row = chunk >> 3, c16 = chunk & 7;
            cp16(bs + SWZ(row * 128 + c16 * 16),
                 bb + bBase + (size_t)row * (DIM * 2) + c16 * 16);
        }
    };

    // per-lane ldmatrix address components (within a stage)
    // A (m16k16 via x4): row = wm*64 + mt*16 + (lane&15), kbyte = (lane>>4)*16
    uint32_t arow[4], amask[4];
    #pragma unroll
    for (int mt = 0; mt < 4; mt++) {
        int row = wm * 64 + mt * 16 + (lane & 15);
        arow[mt] = row * 128;
        amask[mt] = (row & 7) << 4;
    }
    uint32_t akb = (lane >> 4) << 4;
    // B (n16k16 via x4): nrow = wn*64 + pr*16 + (lane&7) + ((lane>>4)<<3)
    uint32_t brow[4], bmask[4];
    #pragma unroll
    for (int pr = 0; pr < 4; pr++) {
        int nrow = wn * 64 + pr * 16 + (lane & 7) + ((lane >> 4) << 3);
        brow[pr] = nrow * 128;
        bmask[pr] = (nrow & 7) << 4;
    }
    uint32_t bkb = ((lane >> 3) & 1) << 4;

    float acc[4][8][4];
    #pragma unroll
    for (int mt = 0; mt < 4; mt++)
        #pragma unroll
        for (int nt = 0; nt < 8; nt++)
            #pragma unroll
            for (int q = 0; q < 4; q++) acc[mt][nt][q] = 0.f;

    // prologue: load both stages
    load_stage(0, 0);
    asm volatile("cp.async.commit_group;");
    load_stage(1, 1);
    asm volatile("cp.async.commit_group;");

    #pragma unroll 1
    for (int i = 0; i < NKIT; i++) {
        asm volatile("cp.async.wait_group 1;");
        __syncthreads();

        uint32_t aB = base + (i & 1) * ST_BYTES;
        uint32_t bB = aB + A_ST_BYTES;

        #pragma unroll
        for (int ks = 0; ks < 4; ks++) {
            uint32_t a[4][4], b[4][4];
            uint32_t ka = ks * 32 + akb;
            uint32_t kb = ks * 32 + bkb;
            #pragma unroll
            for (int mt = 0; mt < 4; mt++)
                ldsm4(a[mt], aB + arow[mt] + (ka ^ amask[mt]));
            #pragma unroll
            for (int pr = 0; pr < 4; pr++)
                ldsm4(b[pr], bB + brow[pr] + (kb ^ bmask[pr]));
            #pragma unroll
            for (int mt = 0; mt < 4; mt++)
                #pragma unroll
                for (int nt = 0; nt < 8; nt++)
                    mma_f16(acc[mt][nt], a[mt], b[nt >> 1][(nt & 1) * 2],
                            b[nt >> 1][(nt & 1) * 2 + 1]);
        }

        __syncthreads();
        if (i + 2 < NKIT) load_stage(i & 1, i + 2);
        asm volatile("cp.async.commit_group;");        // uniform group accounting
    }

    // epilogue: direct fp32 stores (C frag: rows t/4 + {0,8}, cols 2(t%4)+{0,1})
    float* cbase = out + (size_t)(m0 + wm * 64) * DIM + n0 + wn * 64;
    int crow = lane >> 2;
    int ccol = (lane & 3) * 2;
    #pragma unroll
    for (int mt = 0; mt < 4; mt++)
        #pragma unroll
        for (int nt = 0; nt < 8; nt++)
            #pragma unroll
            for (int h = 0; h < 2; h++) {
                float2 v = make_float2(acc[mt][nt][h * 2], acc[mt][nt][h * 2 + 1]);
                *(float2*)(cbase + (size_t)(mt * 16 + crow + h * 8) * DIM + nt * 8 + ccol) = v;
            }
}

// ---------------- fused epilogue: hyperbolic ops, in place on d_out ----------------
__global__ void k_final(float* __restrict__ io) {
    int r = blockIdx.x;
    float4* row = (float4*)(io + (size_t)r * DIM);
    const float4* bm4 = (const float4*)g_bm;
    float smm = 0.f, smb = 0.f;
    float4 mv[4], bv[4];
    #pragma unroll
    for (int it = 0; it < 4; it++) {
        int c = it * 256 + threadIdx.x;
        float4 m = row[c];
        float4 b = bm4[c];
        mv[it] = m; bv[it] = b;
        smm += m.x * m.x + m.y * m.y + m.z * m.z + m.w * m.w;
        smb += m.x * b.x + m.y * b.y + m.z * b.z + m.w * b.w;
    }
    __shared__ float rmm[8], rmb[8];
    __shared__ float sk1, sk2;
    #pragma unroll
    for (int off = 16; off; off >>= 1) {
        smm += __shfl_down_sync(0xffffffffu, smm, off);
        smb += __shfl_down_sync(0xffffffffu, smb, off);
    }
    if ((threadIdx.x & 31) == 0) { rmm[threadIdx.x >> 5] = smm; rmb[threadIdx.x >> 5] = smb; }
    __syncthreads();
    if (threadIdx.x == 0) {
        float Smm = 0.f, Smb = 0.f;
        #pragma unroll
        for (int i = 0; i < 8; i++) { Smm += rmm[i]; Smb += rmb[i]; }
        float xnraw = fmaxf(g_xn[r], 1e-15f);
        float s = (xnraw > MAXN) ? (MAXN / xnraw) : 1.f;
        float xn = fmaxf(fminf(xnraw, MAXN), 1e-15f);
        float mxnraw = sqrtf(Smm);
        float mxn = fmaxf(s * mxnraw, 1e-15f);
        float at = atanhf(fminf(xn, 1.f - 1e-7f));
        float r_ = tanhf((mxn / xn) * at);
        float cres = r_ * s / mxn;            // res_i = cres * mx_raw_i
        float x2 = cres * cres * Smm;
        float xy = cres * Smb;
        float y2 = g_y2s[0];
        float A = 1.f + 2.f * xy + y2;
        float Bc = 1.f - x2;
        float den = fmaxf(1.f + 2.f * xy + x2 * y2, 1e-15f);
        float n2 = (A * A * x2 + 2.f * A * Bc * xy + Bc * Bc * y2) / (den * den);
        float on = fmaxf(sqrtf(fmaxf(n2, 0.f)), 1e-15f);
        float f = (on > MAXN) ? (MAXN / on) : 1.f;
        sk1 = f * A * cres / den;
        sk2 = f * Bc / den;
    }
    __syncthreads();
    float k1 = sk1, k2 = sk2;
    #pragma unroll
    for (int it = 0; it < 4; it++) {
        int c = it * 256 + threadIdx.x;
        float4 m = mv[it], b = bv[it];
        float4 o;
        o.x = k1 * m.x + k2 * b.x;
        o.y = k1 * m.y + k2 * b.y;
        o.z = k1 * m.z + k2 * b.z;
        o.w = k1 * m.w + k2 * b.w;
        row[c] = o;
    }
}

// ---------------- launch ----------------
extern "C" void kernel_launch(void* const* d_in, const int* in_sizes, int n_in,
                              void* d_out, int out_size) {
    const float* x = nullptr;
    const float* w = nullptr;
    const float* b = nullptr;
    for (int i = 0; i < n_in; i++) {
        if (in_sizes[i] == NB * DIM) x = (const float*)d_in[i];
        else if (in_sizes[i] == DIM * DIM) w = (const float*)d_in[i];
        else if (in_sizes[i] == DIM) b = (const float*)d_in[i];
    }
    float* out = (float*)d_out;

    k_conv_x<<<NB, 256>>>(x);
    k_conv_w<<<4096, 256>>>(w);
    k_bias<<<1, 256>>>(b);

    cudaFuncSetAttribute(k_gemm, cudaFuncAttributeMaxDynamicSharedMemorySize, SMEM_NEED);
    k_gemm<<<2048, 128, SMEM_NEED>>>(out);

    k_final<<<NB, 256>>>(out);
}

// round 7
// speedup vs baseline: 1.1600x; 1.1600x over previous
#include <cuda_runtime.h>
#include <cuda_fp16.h>
#include <cstdint>
#include <cstddef>

// Problem shape (fixed by dataset)
#define NB   8192      // batch rows
#define DIM  4096      // in = out features
#define MAXN 0.99999f  // (1-EPS)/sqrt(C)

// ---------------- scratch (device globals; allocation-free) ----------------
__device__ __half g_xh[(size_t)NB * DIM];
__device__ __half g_wh[(size_t)DIM * DIM];
__device__ float g_xn[NB];     // raw row norms of x
__device__ float g_bm[DIM];    // expmap0(bias)
__device__ float g_y2s[1];     // ||bm||^2

// ---------------- PTX helpers (base sm_103 target ONLY: no tcgen05) --------
__device__ __forceinline__ uint32_t smem_u32(const void* p) {
    uint32_t a;
    asm("{ .reg .u64 t; cvta.to.shared.u64 t, %1; cvt.u32.u64 %0, t; }"
        : "=r"(a) : "l"(p));
    return a;
}

__device__ __forceinline__ void cp16(uint32_t dst, const void* src) {
    asm volatile("cp.async.cg.shared.global [%0], [%1], 16;" :: "r"(dst), "l"(src));
}

__device__ __forceinline__ void ldsm4(uint32_t* r, uint32_t addr) {
    asm volatile("ldmatrix.sync.aligned.m8n8.x4.shared.b16 {%0,%1,%2,%3}, [%4];"
                 : "=r"(r[0]), "=r"(r[1]), "=r"(r[2]), "=r"(r[3]) : "r"(addr));
}

__device__ __forceinline__ void mma_f16(float* c, const uint32_t* a,
                                        uint32_t b0, uint32_t b1) {
    asm volatile(
        "mma.sync.aligned.m16n8k16.row.col.f32.f16.f16.f32 "
        "{%0,%1,%2,%3}, {%4,%5,%6,%7}, {%8,%9}, {%0,%1,%2,%3};"
        : "+f"(c[0]), "+f"(c[1]), "+f"(c[2]), "+f"(c[3])
        : "r"(a[0]), "r"(a[1]), "r"(a[2]), "r"(a[3]), "r"(b0), "r"(b1));
}

#define SWZ(o) ((o) ^ (((o) >> 3) & 0x70))

// ---------------- pre-kernels ----------------
__global__ void k_conv_x(const float* __restrict__ x) {
    int r = blockIdx.x;
    const float4* row = (const float4*)(x + (size_t)r * DIM);
    __half2* orow = (__half2*)(g_xh + (size_t)r * DIM);
    float ss = 0.f;
    #pragma unroll
    for (int it = 0; it < 4; it++) {
        int c = it * 256 + threadIdx.x;
        float4 v = row[c];
        ss += v.x * v.x + v.y * v.y + v.z * v.z + v.w * v.w;
        orow[2 * c]     = __floats2half2_rn(v.x, v.y);
        orow[2 * c + 1] = __floats2half2_rn(v.z, v.w);
    }
    __shared__ float red[8];
    #pragma unroll
    for (int off = 16; off; off >>= 1) ss += __shfl_down_sync(0xffffffffu, ss, off);
    if ((threadIdx.x & 31) == 0) red[threadIdx.x >> 5] = ss;
    __syncthreads();
    if (threadIdx.x == 0) {
        float t = 0.f;
        #pragma unroll
        for (int i = 0; i < 8; i++) t += red[i];
        g_xn[r] = sqrtf(t);
    }
}

__global__ void k_conv_w(const float* __restrict__ w) {
    size_t n = (size_t)DIM * DIM / 4;
    const float4* w4 = (const float4*)w;
    __half2* o2 = (__half2*)g_wh;
    for (size_t i = (size_t)blockIdx.x * blockDim.x + threadIdx.x; i < n;
         i += (size_t)gridDim.x * blockDim.x) {
        float4 v = w4[i];
        o2[2 * i]     = __floats2half2_rn(v.x, v.y);
        o2[2 * i + 1] = __floats2half2_rn(v.z, v.w);
    }
}

__global__ void k_bias(const float* __restrict__ bias) {
    __shared__ float red[8];
    __shared__ float s_t;
    float ss = 0.f;
    for (int c = threadIdx.x; c < DIM; c += 256) { float v = bias[c]; ss += v * v; }
    #pragma unroll
    for (int off = 16; off; off >>= 1) ss += __shfl_down_sync(0xffffffffu, ss, off);
    if ((threadIdx.x & 31) == 0) red[threadIdx.x >> 5] = ss;
    __syncthreads();
    if (threadIdx.x == 0) {
        float t = 0.f;
        #pragma unroll
        for (int i = 0; i < 8; i++) t += red[i];
        float bn = fmaxf(sqrtf(t), 1e-15f);
        float th = tanhf(bn);
        s_t = th / bn;
        g_y2s[0] = th * th;
    }
    __syncthreads();
    float sc = s_t;
    for (int c = threadIdx.x; c < DIM; c += 256) g_bm[c] = sc * bias[c];
}

// ---------------- GEMM: mx_raw = x @ W^T, single fp16 pass ----------------
// CTA tile 128(M) x 128(N) x 64(K), 8 warps (4x2, warp tile 32x64), 3-stage
// cp.async, 2 CTAs/SM. Prefetch cp.asyncs interleaved into the ks loop so
// LSU/crossbar pressure is spread across the iteration (fills ldsm shadows).
// K = 4096 -> 64 BK iterations.
#define STAGES 3
#define NKIT   64
#define A_ST_BYTES 16384           // 128 rows x 128B
#define B_ST_BYTES 16384           // 128 rows x 128B
#define ST_BYTES   (A_ST_BYTES + B_ST_BYTES)   // 32 KB
#define SMEM_NEED  (STAGES * ST_BYTES + 1024)  // ~97 KB -> 2 CTAs/SM

__global__ void __launch_bounds__(256, 2)
k_gemm(float* __restrict__ out) {
    extern __shared__ char dsm[];
    uint32_t base = (smem_u32(dsm) + 1023u) & ~1023u;
    const int tid = threadIdx.x;
    const int wid = tid >> 5;
    const int lane = tid & 31;
    const int wm = wid >> 1;          // 0..3  (M direction, 32 rows each)
    const int wn = wid & 1;           // 0..1  (N direction, 64 cols each)

    // rasterize 64 x 32 tiles in 8x32 supertiles for L2 reuse
    int pid = blockIdx.x;
    int group = pid >> 8;             // / (8*32)
    int rem = pid & 255;
    int pm = group * 8 + (rem & 7);
    int pn = rem >> 3;
    const int m0 = pm * 128, n0 = pn * 128;

    // one A-chunk + one B-chunk of the stage, for pieces t = 0..3
    auto load_piece = [&](int s, int i, int t) {
        int koff = i * 64;                              // element offset in K
        size_t aBase = ((size_t)m0 * DIM + koff) * 2;
        size_t bBase = ((size_t)n0 * DIM + koff) * 2;
        uint32_t as = base + s * ST_BYTES;
        uint32_t bs = as + A_ST_BYTES;
        int chunk = t * 256 + tid;
        int row = chunk >> 3, c16 = chunk & 7;
        uint32_t so = SWZ(row * 128 + c16 * 16);
        size_t go = (size_t)row * (DIM * 2) + c16 * 16;
        cp16(as + so, (const char*)g_xh + aBase + go);
        cp16(bs + so, (const char*)g_wh + bBase + go);
    };

    auto load_stage = [&](int s, int i) {
        #pragma unroll
        for (int t = 0; t < 4; t++) load_piece(s, i, t);
    };

    // per-lane ldmatrix address components (within a stage)
    // A (m16k16 via x4): row = wm*32 + mt*16 + (lane&15), kbyte = (lane>>4)*16
    uint32_t arow[2], amask[2];
    #pragma unroll
    for (int mt = 0; mt < 2; mt++) {
        int row = wm * 32 + mt * 16 + (lane & 15);
        arow[mt] = row * 128;
        amask[mt] = (row & 7) << 4;
    }
    uint32_t akb = (lane >> 4) << 4;
    // B (n16k16 via x4): nrow = wn*64 + pr*16 + (lane&7) + ((lane>>4)<<3)
    uint32_t brow[4], bmask[4];
    #pragma unroll
    for (int pr = 0; pr < 4; pr++) {
        int nrow = wn * 64 + pr * 16 + (lane & 7) + ((lane >> 4) << 3);
        brow[pr] = nrow * 128;
        bmask[pr] = (nrow & 7) << 4;
    }
    uint32_t bkb = ((lane >> 3) & 1) << 4;

    float acc[2][8][4];
    #pragma unroll
    for (int mt = 0; mt < 2; mt++)
        #pragma unroll
        for (int nt = 0; nt < 8; nt++)
            #pragma unroll
            for (int q = 0; q < 4; q++) acc[mt][nt][q] = 0.f;

    // prologue: load stages 0,1
    load_stage(0, 0);
    asm volatile("cp.async.commit_group;");
    load_stage(1, 1);
    asm volatile("cp.async.commit_group;");

    int s_cons = 0, s_load = 2;
    #pragma unroll 1
    for (int i = 0; i < NKIT; i++) {
        asm volatile("cp.async.wait_group 1;");
        __syncthreads();

        uint32_t aB = base + s_cons * ST_BYTES;
        uint32_t bB = aB + A_ST_BYTES;
        s_cons = (s_cons == 2) ? 0 : s_cons + 1;
        const bool pref = (i + 2 < NKIT);

        #pragma unroll
        for (int ks = 0; ks < 4; ks++) {
            uint32_t a[2][4], b[4][4];
            uint32_t ka = ks * 32 + akb;
            uint32_t kb = ks * 32 + bkb;
            #pragma unroll
            for (int mt = 0; mt < 2; mt++)
                ldsm4(a[mt], aB + arow[mt] + (ka ^ amask[mt]));
            #pragma unroll
            for (int pr = 0; pr < 4; pr++)
                ldsm4(b[pr], bB + brow[pr] + (kb ^ bmask[pr]));
            // interleaved prefetch: fills the ldsm->mma dependency shadow
            if (pref) load_piece(s_load, i + 2, ks);
            #pragma unroll
            for (int mt = 0; mt < 2; mt++)
                #pragma unroll
                for (int nt = 0; nt < 8; nt++)
                    mma_f16(acc[mt][nt], a[mt], b[nt >> 1][(nt & 1) * 2],
                            b[nt >> 1][(nt & 1) * 2 + 1]);
        }
        asm volatile("cp.async.commit_group;");        // uniform group accounting
        s_load = (s_load == 2) ? 0 : s_load + 1;
    }

    // epilogue: direct fp32 stores (C frag: rows t/4 + {0,8}, cols 2(t%4)+{0,1})
    float* cbase = out + (size_t)(m0 + wm * 32) * DIM + n0 + wn * 64;
    int crow = lane >> 2;
    int ccol = (lane & 3) * 2;
    #pragma unroll
    for (int mt = 0; mt < 2; mt++)
        #pragma unroll
        for (int nt = 0; nt < 8; nt++)
            #pragma unroll
            for (int h = 0; h < 2; h++) {
                float2 v = make_float2(acc[mt][nt][h * 2], acc[mt][nt][h * 2 + 1]);
                *(float2*)(cbase + (size_t)(mt * 16 + crow + h * 8) * DIM + nt * 8 + ccol) = v;
            }
}

// ---------------- fused epilogue: hyperbolic ops, in place on d_out ----------------
__global__ void k_final(float* __restrict__ io) {
    int r = blockIdx.x;
    float4* row = (float4*)(io + (size_t)r * DIM);
    const float4* bm4 = (const float4*)g_bm;
    float smm = 0.f, smb = 0.f;
    float4 mv[4], bv[4];
    #pragma unroll
    for (int it = 0; it < 4; it++) {
        int c = it * 256 + threadIdx.x;
        float4 m = row[c];
        float4 b = bm4[c];
        mv[it] = m; bv[it] = b;
        smm += m.x * m.x + m.y * m.y + m.z * m.z + m.w * m.w;
        smb += m.x * b.x + m.y * b.y + m.z * b.z + m.w * b.w;
    }
    __shared__ float rmm[8], rmb[8];
    __shared__ float sk1, sk2;
    #pragma unroll
    for (int off = 16; off; off >>= 1) {
        smm += __shfl_down_sync(0xffffffffu, smm, off);
        smb += __shfl_down_sync(0xffffffffu, smb, off);
    }
    if ((threadIdx.x & 31) == 0) { rmm[threadIdx.x >> 5] = smm; rmb[threadIdx.x >> 5] = smb; }
    __syncthreads();
    if (threadIdx.x == 0) {
        float Smm = 0.f, Smb = 0.f;
        #pragma unroll
        for (int i = 0; i < 8; i++) { Smm += rmm[i]; Smb += rmb[i]; }
        float xnraw = fmaxf(g_xn[r], 1e-15f);
        float s = (xnraw > MAXN) ? (MAXN / xnraw) : 1.f;
        float xn = fmaxf(fminf(xnraw, MAXN), 1e-15f);
        float mxnraw = sqrtf(Smm);
        float mxn = fmaxf(s * mxnraw, 1e-15f);
        float at = atanhf(fminf(xn, 1.f - 1e-7f));
        float r_ = tanhf((mxn / xn) * at);
        float cres = r_ * s / mxn;            // res_i = cres * mx_raw_i
        float x2 = cres * cres * Smm;
        float xy = cres * Smb;
        float y2 = g_y2s[0];
        float A = 1.f + 2.f * xy + y2;
        float Bc = 1.f - x2;
        float den = fmaxf(1.f + 2.f * xy + x2 * y2, 1e-15f);
        float n2 = (A * A * x2 + 2.f * A * Bc * xy + Bc * Bc * y2) / (den * den);
        float on = fmaxf(sqrtf(fmaxf(n2, 0.f)), 1e-15f);
        float f = (on > MAXN) ? (MAXN / on) : 1.f;
        sk1 = f * A * cres / den;
        sk2 = f * Bc / den;
    }
    __syncthreads();
    float k1 = sk1, k2 = sk2;
    #pragma unroll
    for (int it = 0; it < 4; it++) {
        int c = it * 256 + threadIdx.x;
        float4 m = mv[it], b = bv[it];
        float4 o;
        o.x = k1 * m.x + k2 * b.x;
        o.y = k1 * m.y + k2 * b.y;
        o.z = k1 * m.z + k2 * b.z;
        o.w = k1 * m.w + k2 * b.w;
        row[c] = o;
    }
}

// ---------------- launch ----------------
extern "C" void kernel_launch(void* const* d_in, const int* in_sizes, int n_in,
                              void* d_out, int out_size) {
    const float* x = nullptr;
    const float* w = nullptr;
    const float* b = nullptr;
    for (int i = 0; i < n_in; i++) {
        if (in_sizes[i] == NB * DIM) x = (const float*)d_in[i];
        else if (in_sizes[i] == DIM * DIM) w = (const float*)d_in[i];
        else if (in_sizes[i] == DIM) b = (const float*)d_in[i];
    }
    float* out = (float*)d_out;

    k_conv_x<<<NB, 256>>>(x);
    k_conv_w<<<4096, 256>>>(w);
    k_bias<<<1, 256>>>(b);

    cudaFuncSetAttribute(k_gemm, cudaFuncAttributeMaxDynamicSharedMemorySize, SMEM_NEED);
    k_gemm<<<2048, 256, SMEM_NEED>>>(out);

    k_final<<<NB, 256>>>(out);
}